// round 6
// baseline (speedup 1.0000x reference)
#include <cuda_runtime.h>

#define S_ 512
#define L_ 256
#define H_ 768
#define P_ 8
#define K_ 8
#define H4_ 192             // float4 per full row
#define HH4_ 96             // float4 per half row
#define SEG_ 68             // per-role segment capacity (64 max + pad slack)
#define THREADS_ 96
#define MAXB_ 51            // max batches: 3 * ceil(64/4)

__global__ __launch_bounds__(THREADS_, 1)
void srl_pool_kernel(const float* __restrict__ emb,
                     const int* __restrict__ idxV,  const int* __restrict__ mV,
                     const int* __restrict__ idxA0, const int* __restrict__ mA0,
                     const int* __restrict__ idxA1, const int* __restrict__ mA1,
                     const int* __restrict__ pred,
                     float* __restrict__ out)
{
    const int s     = blockIdx.x;
    const int hhalf = blockIdx.y;
    const int tid   = threadIdx.x;

    __shared__ int   s_idx[3 * SEG_];
    __shared__ float s_w[3 * SEG_];
    __shared__ int   b_off[MAXB_];
    __shared__ int   b_role[MAXB_];
    __shared__ int   s_nb;

    // Zero lists so padded slots are (idx=0, w=0) — harmless row-0 loads.
    for (int j = tid; j < 3 * SEG_; j += THREADS_) { s_idx[j] = 0; s_w[j] = 0.0f; }
    __syncthreads();

    // ---------- Phase 1: warp-scan compaction (lanes 0..23 of warp 0) ----------
    if (tid < 3 * P_) {
        const unsigned FULL = 0x00FFFFFFu;
        const int role = tid >> 3;
        const int p    = tid & 7;
        const int* __restrict__ idx =
            (role == 0) ? idxV : (role == 1) ? idxA0 : idxA1;
        const int* __restrict__ msk =
            (role == 0) ? mV : (role == 1) ? mA0 : mA1;

        const int base = (s * P_ + p) * K_;
        int4 iv0 = *reinterpret_cast<const int4*>(idx + base);
        int4 iv1 = *reinterpret_cast<const int4*>(idx + base + 4);
        int4 mv0 = *reinterpret_cast<const int4*>(msk + base);
        int4 mv1 = *reinterpret_cast<const int4*>(msk + base + 4);
        int4 pv0 = *reinterpret_cast<const int4*>(pred + s * P_);
        int4 pv1 = *reinterpret_cast<const int4*>(pred + s * P_ + 4);

        int li[K_] = { iv0.x, iv0.y, iv0.z, iv0.w, iv1.x, iv1.y, iv1.z, iv1.w };
        int lm[K_] = { mv0.x, mv0.y, mv0.z, mv0.w, mv1.x, mv1.y, mv1.z, mv1.w };

        int lv[K_];
        int cnt = 0;
        #pragma unroll
        for (int k = 0; k < K_; k++) {
            int v = (lm[k] != 0) & (li[k] < L_) & (li[k] >= 0);
            li[k] = min(max(li[k], 0), L_ - 1);
            lv[k] = v;
            cnt  += v;
        }

        int pown  = (p < 4) ? ((const int*)&pv0)[p] : ((const int*)&pv1)[p - 4];
        int npred = (pv0.x != 0) + (pv0.y != 0) + (pv0.z != 0) + (pv0.w != 0)
                  + (pv1.x != 0) + (pv1.y != 0) + (pv1.z != 0) + (pv1.w != 0);

        float w = 0.0f;
        int take = (pown != 0 && cnt > 0 && npred > 0);
        if (take) w = 1.0f / ((float)cnt * (float)npred);
        int eff = take ? cnt : 0;   // entries this lane contributes

        // Inclusive prefix of eff within each 8-lane role group.
        int off = eff;
        #pragma unroll
        for (int d = 1; d < 8; d <<= 1) {
            int y = __shfl_up_sync(FULL, off, d);
            if (p >= d) off += y;
        }
        int excl = off - eff;

        if (take) {
            int pos = role * SEG_ + excl;
            #pragma unroll
            for (int k = 0; k < K_; k++) {
                if (lv[k]) {
                    s_idx[pos] = li[k];
                    s_w[pos]   = w;
                    pos++;
                }
            }
        }

        // Role totals live on lanes 7, 15, 23.
        int t0 = __shfl_sync(FULL, off, 7);
        int t1 = __shfl_sync(FULL, off, 15);
        int t2 = __shfl_sync(FULL, off, 23);

        if (tid == 0) {
            int ns[3] = { t0, t1, t2 };
            int nb = 0;
            #pragma unroll
            for (int r = 0; r < 3; r++) {
                int np = (ns[r] + 3) & ~3;
                for (int j = 0; j < np; j += 4) {
                    b_off[nb]  = r * SEG_ + j;
                    b_role[nb] = r;
                    nb++;
                }
            }
            s_nb = nb;
        }
    }
    __syncthreads();

    // ---------- Phase 2: depth-3 software-pipelined gather/accumulate ----------
    const float4* __restrict__ embc =
        reinterpret_cast<const float4*>(emb) + (size_t)s * L_ * H4_ + hhalf * HH4_ + tid;

    float4 a0 = make_float4(0.f, 0.f, 0.f, 0.f);
    float4 a1 = a0, a2 = a0;

    const int nb = s_nb;

    float4 vA0, vA1, vA2, vA3, wA; int rA;
    float4 vB0, vB1, vB2, vB3, wB; int rB;
    float4 vC0, vC1, vC2, vC3, wC; int rC;

    #define LOADB(V0, V1, V2, V3, W, R, BB) do {                               \
        int bc = ((BB) < nb) ? (BB) : (nb - 1);                                \
        int o  = b_off[bc];                                                    \
        R = b_role[bc];                                                        \
        float m = ((BB) < nb) ? 1.0f : 0.0f;                                   \
        int i0 = s_idx[o+0], i1 = s_idx[o+1], i2 = s_idx[o+2], i3 = s_idx[o+3];\
        W.x = m * s_w[o+0]; W.y = m * s_w[o+1];                                \
        W.z = m * s_w[o+2]; W.w = m * s_w[o+3];                                \
        V0 = embc[i0 * H4_]; V1 = embc[i1 * H4_];                              \
        V2 = embc[i2 * H4_]; V3 = embc[i3 * H4_];                              \
    } while (0)

    #define FMA16(A, W, V0, V1, V2, V3) do {                                   \
        A.x += W.x*V0.x; A.y += W.x*V0.y; A.z += W.x*V0.z; A.w += W.x*V0.w;    \
        A.x += W.y*V1.x; A.y += W.y*V1.y; A.z += W.y*V1.z; A.w += W.y*V1.w;    \
        A.x += W.z*V2.x; A.y += W.z*V2.y; A.z += W.z*V2.z; A.w += W.z*V2.w;    \
        A.x += W.w*V3.x; A.y += W.w*V3.y; A.z += W.w*V3.z; A.w += W.w*V3.w;    \
    } while (0)

    #define CONSUME(V0, V1, V2, V3, W, R) do {                                 \
        if (R == 0)      { FMA16(a0, W, V0, V1, V2, V3); }                     \
        else if (R == 1) { FMA16(a1, W, V0, V1, V2, V3); }                     \
        else             { FMA16(a2, W, V0, V1, V2, V3); }                     \
    } while (0)

    if (nb > 0) {
        LOADB(vA0, vA1, vA2, vA3, wA, rA, 0);
        LOADB(vB0, vB1, vB2, vB3, wB, rB, 1);
        LOADB(vC0, vC1, vC2, vC3, wC, rC, 2);
        int b = 0, next = 3;
        for (;;) {
            CONSUME(vA0, vA1, vA2, vA3, wA, rA);
            if (++b >= nb) break;
            LOADB(vA0, vA1, vA2, vA3, wA, rA, next); next++;

            CONSUME(vB0, vB1, vB2, vB3, wB, rB);
            if (++b >= nb) break;
            LOADB(vB0, vB1, vB2, vB3, wB, rB, next); next++;

            CONSUME(vC0, vC1, vC2, vC3, wC, rC);
            if (++b >= nb) break;
            LOADB(vC0, vC1, vC2, vC3, wC, rC, next); next++;
        }
    }

    #undef LOADB
    #undef FMA16
    #undef CONSUME

    // Output: (e_V, e_A0, e_A1) role-major, each (S, H) f32.
    float4* __restrict__ out4 =
        reinterpret_cast<float4*>(out) + (size_t)s * H4_ + hhalf * HH4_ + tid;
    out4[(size_t)0 * S_ * H4_] = a0;
    out4[(size_t)1 * S_ * H4_] = a1;
    out4[(size_t)2 * S_ * H4_] = a2;
}

extern "C" void kernel_launch(void* const* d_in, const int* in_sizes, int n_in,
                              void* d_out, int out_size)
{
    const float* emb   = (const float*)d_in[0];
    const int*   idxV  = (const int*)d_in[1];
    const int*   mV    = (const int*)d_in[2];
    const int*   idxA0 = (const int*)d_in[3];
    const int*   mA0   = (const int*)d_in[4];
    const int*   idxA1 = (const int*)d_in[5];
    const int*   mA1   = (const int*)d_in[6];
    const int*   pred  = (const int*)d_in[7];
    float* out = (float*)d_out;

    dim3 grid(S_, 2);
    srl_pool_kernel<<<grid, THREADS_>>>(emb, idxV, mV, idxA0, mA0, idxA1, mA1, pred, out);
}